// round 3
// baseline (speedup 1.0000x reference)
#include <cuda_runtime.h>
#include <math.h>

// Model dims
#define BB 64
#define SS 128
#define FF 16
#define HH 64
#define ATTN_ELEMS (16u*64u*128u*128u)

typedef unsigned long long u64;

// Scratch (allocation-free rule: __device__ globals)
__device__ float g_lstm[2ull*BB*FF*SS*HH];   // [br][b][f][s][h]  (67 MB)
__device__ float g_pooled[2ull*BB*FF*HH];    // [br][b][f][h]

// ---- packed f32x2 helpers (PTX-only FFMA2 path) ----
__device__ __forceinline__ u64 pk2(float lo, float hi){
    u64 r; asm("mov.b64 %0, {%1, %2};" : "=l"(r) : "f"(lo), "f"(hi)); return r;
}
__device__ __forceinline__ void upk2(u64 v, float& lo, float& hi){
    asm("mov.b64 {%0, %1}, %2;" : "=f"(lo), "=f"(hi) : "l"(v));
}
__device__ __forceinline__ u64 ffma2(u64 a, u64 b, u64 c){
    u64 d; asm("fma.rn.f32x2 %0, %1, %2, %3;" : "=l"(d) : "l"(a), "l"(b), "l"(c)); return d;
}
__device__ __forceinline__ u64 fadd2(u64 a, u64 b){
    u64 d; asm("add.rn.f32x2 %0, %1, %2;" : "=l"(d) : "l"(a), "l"(b)); return d;
}
__device__ __forceinline__ u64 fmul2(u64 a, u64 b){
    u64 d; asm("mul.rn.f32x2 %0, %1, %2;" : "=l"(d) : "l"(a), "l"(b)); return d;
}
__device__ __forceinline__ float hsum2(u64 v){ float lo,hi; upk2(v,lo,hi); return lo+hi; }

__device__ __forceinline__ float sigf(float x){ return 1.f/(1.f+__expf(-x)); }
__device__ __forceinline__ float tanhfast(float x){ return 2.f/(1.f+__expf(-2.f*x)) - 1.f; }

// 64-float dot: w (16B-aligned smem/any), xp = 32 packed u64 register operand
__device__ __forceinline__ float dot64p(const float* __restrict__ w, const u64* xp){
    const ulonglong2* W2 = (const ulonglong2*)w;
    u64 a0=0ull,a1=0ull,a2=0ull,a3=0ull;
    #pragma unroll
    for (int j = 0; j < 8; j++) {
        ulonglong2 w0 = W2[2*j];
        ulonglong2 w1 = W2[2*j+1];
        a0 = ffma2(w0.x, xp[4*j+0], a0);
        a1 = ffma2(w0.y, xp[4*j+1], a1);
        a2 = ffma2(w1.x, xp[4*j+2], a2);
        a3 = ffma2(w1.y, xp[4*j+3], a3);
    }
    return hsum2(fadd2(fadd2(a0,a1),fadd2(a2,a3)));
}

// ---------------------------------------------------------------------------
// LSTM: one block per (branch, f, 4-batch tile). 256 threads.
// Phase 1: thread g computes gate row g for 4 batches (weights in regs, x4 reuse).
// Phase 2: thread t = (batch b2 = t>>6, unit u = t&63) does elementwise + h store.
// ---------------------------------------------------------------------------
#define BT 4   // batch tile

__global__ __launch_bounds__(256,2) void lstm_kernel(
    const float* __restrict__ wd_x, const float* __restrict__ rd_x,
    const float* __restrict__ wd_Wih, const float* __restrict__ wd_Whh,
    const float* __restrict__ wd_bih, const float* __restrict__ wd_bhh,
    const float* __restrict__ rd_Wih, const float* __restrict__ rd_Whh,
    const float* __restrict__ rd_bih, const float* __restrict__ rd_bhh)
{
    int idx = blockIdx.x;              // [br(1)][f(4)][bt(4)] bits
    int br = idx >> 8;
    int f  = (idx >> 4) & 15;
    int b0 = (idx & 15) * BT;
    const float* x   = br ? rd_x   : wd_x;
    const float* Wih = br ? rd_Wih : wd_Wih;
    const float* Whh = br ? rd_Whh : wd_Whh;
    const float* bih = br ? rd_bih : wd_bih;
    const float* bhh = br ? rd_bhh : wd_bhh;
    int g = threadIdx.x;

    __shared__ __align__(16) float sh_h[BT*64];
    __shared__ float sh_x[BT*128];
    __shared__ float sh_g[BT*256];

    u64 wp[32];
    {
        const float4* wr4 = (const float4*)(Whh + ((size_t)f*256 + g)*64);
        #pragma unroll
        for (int j = 0; j < 16; j++) {
            float4 v = wr4[j];
            wp[2*j]   = pk2(v.x, v.y);
            wp[2*j+1] = pk2(v.z, v.w);
        }
    }
    float wih  = Wih[f*256+g];
    float bias = bih[f*256+g] + bhh[f*256+g];

    // stage x for the 4 batches: sh_x[b][s]
    for (int i = g; i < BT*128; i += 256) {
        int b = i >> 7, s = i & 127;
        sh_x[i] = x[((size_t)(b0+b)*128 + s)*16 + f];
    }
    if (g < BT*64) sh_h[g] = 0.f;

    // phase-2 identity for this thread
    int b2 = g >> 6, u = g & 63;
    float c = 0.f;
    float* outpT = g_lstm + (((size_t)br*BB + (b0+b2))*FF + f)*(size_t)(SS*HH) + u;
    __syncthreads();

    for (int s = 0; s < 128; s++) {
        // ---- phase 1: 4 dot products against the register-resident weight row
        u64 acc0[BT], acc1[BT];
        #pragma unroll
        for (int b = 0; b < BT; b++) { acc0[b]=0ull; acc1[b]=0ull; }
        #pragma unroll
        for (int j = 0; j < 16; j += 2) {
            ulonglong2 h0[BT], h1[BT];
            #pragma unroll
            for (int b = 0; b < BT; b++) {
                const ulonglong2* Hb = (const ulonglong2*)(sh_h + b*64);
                h0[b] = Hb[j]; h1[b] = Hb[j+1];
            }
            #pragma unroll
            for (int b = 0; b < BT; b++) {
                acc0[b] = ffma2(wp[2*j],   h0[b].x, acc0[b]);
                acc1[b] = ffma2(wp[2*j+1], h0[b].y, acc1[b]);
                acc0[b] = ffma2(wp[2*j+2], h1[b].x, acc0[b]);
                acc1[b] = ffma2(wp[2*j+3], h1[b].y, acc1[b]);
            }
        }
        #pragma unroll
        for (int b = 0; b < BT; b++) {
            sh_g[b*256 + g] = fmaf(sh_x[b*128 + s], wih, bias)
                            + hsum2(fadd2(acc0[b], acc1[b]));
        }
        __syncthreads();
        // ---- phase 2: elementwise, one (batch,unit) per thread
        {
            const float* gb = sh_g + b2*256;
            float ig = sigf(gb[u]);
            float fg = sigf(gb[64+u]);
            float gg = tanhfast(gb[128+u]);
            float og = sigf(gb[192+u]);
            c = fg*c + ig*gg;
            float h = og*tanhfast(c);
            sh_h[b2*64 + u] = h;
            outpT[s*64] = h;
        }
        __syncthreads();
    }
}

// ---------------------------------------------------------------------------
// Attention: one block per (branch, b, f). 128 threads; thread t = query row t.
// Two-pass softmax (no max-subtraction; scores are tiny), no score buffers.
// ---------------------------------------------------------------------------
#define KV_STRIDE 68
#define SM_K     0
#define SM_V     (128*KV_STRIDE)
#define SM_WBUF  (2*128*KV_STRIDE)            // 2048 floats
#define SM_WTR   (SM_WBUF + 2048)             // 128*33 = 4224 floats
#define SM_BIN   (SM_WTR + 128*33)            // 192
#define SM_BOUT  (SM_BIN + 192)               // 64
#define SM_RED   (SM_BOUT + 64)               // 256
#define ATTN_SMEM_FLOATS (SM_RED + 256)
#define ATTN_SMEM_BYTES  (ATTN_SMEM_FLOATS*4)

__global__ __launch_bounds__(128,2) void attn_kernel(
    const float* __restrict__ wd_aw, const float* __restrict__ wd_ab,
    const float* __restrict__ wd_ow, const float* __restrict__ wd_ob,
    const float* __restrict__ rd_aw, const float* __restrict__ rd_ab,
    const float* __restrict__ rd_ow, const float* __restrict__ rd_ob,
    float* __restrict__ out_base)
{
    extern __shared__ __align__(16) float sm[];
    float* Ksm   = sm + SM_K;
    float* Vsm   = sm + SM_V;
    float* Wbuf  = sm + SM_WBUF;
    float* wtr   = sm + SM_WTR;
    float* binsm = sm + SM_BIN;
    float* boutsm= sm + SM_BOUT;
    float* red   = sm + SM_RED;

    int idx = blockIdx.x;
    int br = idx >> 10;
    int b  = (idx >> 4) & 63;
    int f  = idx & 15;
    int t  = threadIdx.x;
    const float* aw = (br ? rd_aw : wd_aw) + (size_t)f*192*64;
    const float* ab = (br ? rd_ab : wd_ab) + f*192;
    const float* ow = (br ? rd_ow : wd_ow) + (size_t)f*64*64;
    const float* ob = (br ? rd_ob : wd_ob) + f*64;

    // biases
    for (int i = t; i < 192; i += 128) binsm[i] = ab[i];
    if (t < 64) boutsm[t] = ob[t];

    // my LSTM row (S-position t), packed
    u64 xp[32];
    {
        const ulonglong2* X2 = (const ulonglong2*)(g_lstm +
            (((size_t)br*BB + b)*FF + f)*(size_t)(SS*HH) + (size_t)t*64);
        #pragma unroll
        for (int j = 0; j < 16; j++) {
            ulonglong2 v = X2[j];
            xp[2*j] = v.x; xp[2*j+1] = v.y;
        }
    }

    // ---- Phase A: QKV projection in 32-row weight chunks ----
    #pragma unroll 1
    for (int c = 0; c < 2; c++) {            // K
        __syncthreads();
        const float4* src = (const float4*)(aw + (size_t)(64 + 32*c)*64);
        for (int i = t; i < 512; i += 128) ((float4*)Wbuf)[i] = src[i];
        __syncthreads();
        #pragma unroll 2
        for (int r = 0; r < 32; r++) {
            float v = dot64p(Wbuf + r*64, xp) + binsm[64 + 32*c + r];
            Ksm[t*KV_STRIDE + 32*c + r] = v;
        }
    }
    #pragma unroll 1
    for (int c = 0; c < 2; c++) {            // V
        __syncthreads();
        const float4* src = (const float4*)(aw + (size_t)(128 + 32*c)*64);
        for (int i = t; i < 512; i += 128) ((float4*)Wbuf)[i] = src[i];
        __syncthreads();
        #pragma unroll 2
        for (int r = 0; r < 32; r++) {
            float v = dot64p(Wbuf + r*64, xp) + binsm[128 + 32*c + r];
            Vsm[t*KV_STRIDE + 32*c + r] = v;
        }
    }
    u64 qp[32];
    #pragma unroll 1
    for (int c = 0; c < 2; c++) {            // q (kept packed in regs)
        __syncthreads();
        const float4* src = (const float4*)(aw + (size_t)(32*c)*64);
        for (int i = t; i < 512; i += 128) ((float4*)Wbuf)[i] = src[i];
        __syncthreads();
        if (c == 0) {
            #pragma unroll
            for (int i = 0; i < 16; i++) {
                float d0 = dot64p(Wbuf + (2*i)*64,   xp) + binsm[2*i];
                float d1 = dot64p(Wbuf + (2*i+1)*64, xp) + binsm[2*i+1];
                qp[i] = pk2(d0, d1);
            }
        } else {
            #pragma unroll
            for (int i = 0; i < 16; i++) {
                float d0 = dot64p(Wbuf + (2*i)*64,   xp) + binsm[32+2*i];
                float d1 = dot64p(Wbuf + (2*i+1)*64, xp) + binsm[32+2*i+1];
                qp[16+i] = pk2(d0, d1);
            }
        }
    }

    const float scale = 0.1767766952966369f; // 1/sqrt(32)

    // ---- Pass 1: scores -> exp (no max-sub) -> unnormalized O + sums ----
    u64 op[32];
    #pragma unroll
    for (int j = 0; j < 32; j++) op[j] = 0ull;
    float sum0 = 0.f, sum1 = 0.f;
    #pragma unroll 2
    for (int k = 0; k < 128; k++) {
        const ulonglong2* Kr = (const ulonglong2*)(Ksm + k*KV_STRIDE);
        u64 b0=0ull,b1=0ull,c0=0ull,c1=0ull;
        #pragma unroll
        for (int j = 0; j < 8; j++) {
            ulonglong2 kv = Kr[j];
            b0 = ffma2(kv.x, qp[2*j],   b0);
            b1 = ffma2(kv.y, qp[2*j+1], b1);
        }
        #pragma unroll
        for (int j = 8; j < 16; j++) {
            ulonglong2 kv = Kr[j];
            c0 = ffma2(kv.x, qp[2*j],   c0);
            c1 = ffma2(kv.y, qp[2*j+1], c1);
        }
        float s0 = hsum2(fadd2(b0,b1)) * scale;
        float s1 = hsum2(fadd2(c0,c1)) * scale;
        float e0 = __expf(s0), e1 = __expf(s1);
        sum0 += e0; sum1 += e1;
        u64 w0 = pk2(e0,e0), w1 = pk2(e1,e1);
        const ulonglong2* Vr = (const ulonglong2*)(Vsm + k*KV_STRIDE);
        #pragma unroll
        for (int j = 0; j < 8; j++) {
            ulonglong2 vv = Vr[j];
            op[2*j]   = ffma2(w0, vv.x, op[2*j]);
            op[2*j+1] = ffma2(w0, vv.y, op[2*j+1]);
        }
        #pragma unroll
        for (int j = 8; j < 16; j++) {
            ulonglong2 vv = Vr[j];
            op[2*j]   = ffma2(w1, vv.x, op[2*j]);
            op[2*j+1] = ffma2(w1, vv.y, op[2*j+1]);
        }
    }
    float inv0 = 1.f/sum0, inv1 = 1.f/sum1;
    {
        u64 i0 = pk2(inv0, inv0), i1 = pk2(inv1, inv1);
        #pragma unroll
        for (int j = 0; j < 16; j++) op[j] = fmul2(op[j], i0);
        #pragma unroll
        for (int j = 16; j < 32; j++) op[j] = fmul2(op[j], i1);
    }

    // ---- Pass 2: recompute scores, write head-avg attn weights (coalesced
    //      via 128x33 transpose tile) ----
    float* outw = out_base + 128 + (size_t)br*ATTN_ELEMS + (((size_t)f*64 + b) << 14);
    #pragma unroll 1
    for (int kc = 0; kc < 4; kc++) {
        #pragma unroll 2
        for (int kk = 0; kk < 32; kk++) {
            int k = kc*32 + kk;
            const ulonglong2* Kr = (const ulonglong2*)(Ksm + k*KV_STRIDE);
            u64 b0=0ull,b1=0ull,c0=0ull,c1=0ull;
            #pragma unroll
            for (int j = 0; j < 8; j++) {
                ulonglong2 kv = Kr[j];
                b0 = ffma2(kv.x, qp[2*j],   b0);
                b1 = ffma2(kv.y, qp[2*j+1], b1);
            }
            #pragma unroll
            for (int j = 8; j < 16; j++) {
                ulonglong2 kv = Kr[j];
                c0 = ffma2(kv.x, qp[2*j],   c0);
                c1 = ffma2(kv.y, qp[2*j+1], c1);
            }
            float s0 = hsum2(fadd2(b0,b1)) * scale;
            float s1 = hsum2(fadd2(c0,c1)) * scale;
            wtr[t*33 + kk] = 0.5f*(__expf(s0)*inv0 + __expf(s1)*inv1);
        }
        __syncthreads();
        for (int i = t; i < 4096; i += 128) {
            int r = i >> 5, cc = i & 31;
            outw[r*128 + kc*32 + cc] = wtr[r*33 + cc];
        }
        __syncthreads();
    }

    // ---- Phase C: out-projection + mean over S. Stage Wout into Ksm (free). ----
    for (int i = t; i < 1024; i += 128) ((float4*)Ksm)[i] = ((const float4*)ow)[i];
    __syncthreads();
    int lane = t & 31, warp = t >> 5;
    #pragma unroll 2
    for (int o = 0; o < 64; o++) {
        float acc = dot64p(Ksm + o*64, op);
        #pragma unroll
        for (int off = 16; off; off >>= 1)
            acc += __shfl_down_sync(0xffffffffu, acc, off);
        if (lane == 0) red[warp*64 + o] = acc;
    }
    __syncthreads();
    if (t < 64) {
        float s = red[t] + red[64+t] + red[128+t] + red[192+t];
        g_pooled[(((size_t)br*BB + b)*FF + f)*HH + t] = s*(1.f/128.f) + boutsm[t];
    }
}

// ---------------------------------------------------------------------------
// Head: static/time MLPs + final fc. One block, thread = batch row.
// ---------------------------------------------------------------------------
__global__ __launch_bounds__(64) void head_kernel(
    const float* __restrict__ stat, const float* __restrict__ tg,
    const float* __restrict__ d1w, const float* __restrict__ d1b,
    const float* __restrict__ d2w, const float* __restrict__ d2b,
    const float* __restrict__ t1w, const float* __restrict__ t1b,
    const float* __restrict__ t2w, const float* __restrict__ t2b,
    const float* __restrict__ fcw, const float* __restrict__ fcb,
    float* __restrict__ out)
{
    int b = threadIdx.x;
    float s1[64];
    #pragma unroll
    for (int j = 0; j < 64; j++) {
        float acc = d1b[j];
        #pragma unroll
        for (int k = 0; k < 32; k++) acc += stat[b*32+k]*d1w[j*32+k];
        s1[j] = fmaxf(acc, 0.f);
    }
    float s2[32];
    #pragma unroll
    for (int j = 0; j < 32; j++) {
        float acc = d2b[j];
        #pragma unroll
        for (int k = 0; k < 64; k++) acc += s1[k]*d2w[j*64+k];
        s2[j] = fmaxf(acc, 0.f);
    }
    float tv = tg[b];
    float tt1[16];
    #pragma unroll
    for (int j = 0; j < 16; j++) tt1[j] = fmaxf(t1b[j] + tv*t1w[j], 0.f);
    float tt2[8];
    #pragma unroll
    for (int j = 0; j < 8; j++) {
        float acc = t2b[j];
        #pragma unroll
        for (int k = 0; k < 16; k++) acc += tt1[k]*t2w[j*16+k];
        tt2[j] = fmaxf(acc, 0.f);
    }
    const float* p_wd = g_pooled + (size_t)b*1024;
    const float* p_rd = g_pooled + 65536u + (size_t)b*1024;
    #pragma unroll
    for (int o = 0; o < 2; o++) {
        const float* w = fcw + o*2088;
        float acc = fcb[o];
        for (int i = 0; i < 1024; i++) acc += p_wd[i]*w[i];
        for (int i = 0; i < 1024; i++) acc += p_rd[i]*w[1024+i];
        #pragma unroll
        for (int k = 0; k < 32; k++) acc += s2[k]*w[2048+k];
        #pragma unroll
        for (int k = 0; k < 8; k++)  acc += tt2[k]*w[2080+k];
        out[b*2+o] = acc;
    }
}

// ---------------------------------------------------------------------------
extern "C" void kernel_launch(void* const* d_in, const int* in_sizes, int n_in,
                              void* d_out, int out_size)
{
    const float* wd_x   = (const float*)d_in[0];
    const float* rd_x   = (const float*)d_in[1];
    const float* stat   = (const float*)d_in[2];
    const float* tg     = (const float*)d_in[3];
    const float* wd_Wih = (const float*)d_in[4];
    const float* wd_Whh = (const float*)d_in[5];
    const float* wd_bih = (const float*)d_in[6];
    const float* wd_bhh = (const float*)d_in[7];
    const float* rd_Wih = (const float*)d_in[8];
    const float* rd_Whh = (const float*)d_in[9];
    const float* rd_bih = (const float*)d_in[10];
    const float* rd_bhh = (const float*)d_in[11];
    const float* wd_aw  = (const float*)d_in[12];
    const float* wd_ab  = (const float*)d_in[13];
    const float* wd_ow  = (const float*)d_in[14];
    const float* wd_ob  = (const float*)d_in[15];
    const float* rd_aw  = (const float*)d_in[16];
    const float* rd_ab  = (const float*)d_in[17];
    const float* rd_ow  = (const float*)d_in[18];
    const float* rd_ob  = (const float*)d_in[19];
    const float* d1w = (const float*)d_in[20];
    const float* d1b = (const float*)d_in[21];
    const float* d2w = (const float*)d_in[22];
    const float* d2b = (const float*)d_in[23];
    const float* t1w = (const float*)d_in[24];
    const float* t1b = (const float*)d_in[25];
    const float* t2w = (const float*)d_in[26];
    const float* t2b = (const float*)d_in[27];
    const float* fcw = (const float*)d_in[28];
    const float* fcb = (const float*)d_in[29];
    float* out = (float*)d_out;

    cudaFuncSetAttribute(attn_kernel,
                         cudaFuncAttributeMaxDynamicSharedMemorySize,
                         ATTN_SMEM_BYTES);

    lstm_kernel<<<512, 256>>>(wd_x, rd_x, wd_Wih, wd_Whh, wd_bih, wd_bhh,
                              rd_Wih, rd_Whh, rd_bih, rd_bhh);
    attn_kernel<<<2048, 128, ATTN_SMEM_BYTES>>>(wd_aw, wd_ab, wd_ow, wd_ob,
                                                rd_aw, rd_ab, rd_ow, rd_ob, out);
    head_kernel<<<1, 64>>>(stat, tg, d1w, d1b, d2w, d2b,
                           t1w, t1b, t2w, t2b, fcw, fcb, out);
}

// round 4
// speedup vs baseline: 1.4571x; 1.4571x over previous
#include <cuda_runtime.h>
#include <math.h>

// Model dims
#define BB 64
#define SS 128
#define FF 16
#define HH 64
#define ATTN_ELEMS (16u*64u*128u*128u)

typedef unsigned long long u64;

// Scratch (allocation-free rule: __device__ globals)
__device__ float g_lstm[2ull*BB*FF*SS*HH];   // [br][b][f][s][h]  (67 MB)
__device__ float g_pooled[2ull*BB*FF*HH];    // [br][b][f][h]

// ---- packed f32x2 helpers ----
__device__ __forceinline__ u64 pk2(float lo, float hi){
    u64 r; asm("mov.b64 %0, {%1, %2};" : "=l"(r) : "f"(lo), "f"(hi)); return r;
}
__device__ __forceinline__ void upk2(u64 v, float& lo, float& hi){
    asm("mov.b64 {%0, %1}, %2;" : "=f"(lo), "=f"(hi) : "l"(v));
}
__device__ __forceinline__ u64 ffma2(u64 a, u64 b, u64 c){
    u64 d; asm("fma.rn.f32x2 %0, %1, %2, %3;" : "=l"(d) : "l"(a), "l"(b), "l"(c)); return d;
}
__device__ __forceinline__ u64 fadd2(u64 a, u64 b){
    u64 d; asm("add.rn.f32x2 %0, %1, %2;" : "=l"(d) : "l"(a), "l"(b)); return d;
}
__device__ __forceinline__ u64 fmul2(u64 a, u64 b){
    u64 d; asm("mul.rn.f32x2 %0, %1, %2;" : "=l"(d) : "l"(a), "l"(b)); return d;
}
__device__ __forceinline__ float hsum2(u64 v){ float lo,hi; upk2(v,lo,hi); return lo+hi; }

__device__ __forceinline__ float sigf(float x){ return 1.f/(1.f+__expf(-x)); }
__device__ __forceinline__ float tanh_approx(float x){
    float y; asm("tanh.approx.f32 %0, %1;" : "=f"(y) : "f"(x)); return y;
}

// 64-float dot: w (16B-aligned smem), xp = 32 packed u64 register operand
__device__ __forceinline__ float dot64p(const float* __restrict__ w, const u64* xp){
    const ulonglong2* W2 = (const ulonglong2*)w;
    u64 a0=0ull,a1=0ull,a2=0ull,a3=0ull;
    #pragma unroll
    for (int j = 0; j < 8; j++) {
        ulonglong2 w0 = W2[2*j];
        ulonglong2 w1 = W2[2*j+1];
        a0 = ffma2(w0.x, xp[4*j+0], a0);
        a1 = ffma2(w0.y, xp[4*j+1], a1);
        a2 = ffma2(w1.x, xp[4*j+2], a2);
        a3 = ffma2(w1.y, xp[4*j+3], a3);
    }
    return hsum2(fadd2(fadd2(a0,a1),fadd2(a2,a3)));
}

// ---------------------------------------------------------------------------
// LSTM: one block per (branch, b, f). 256 threads, 8 warps.
// lane l of warp w owns (gate-type gt = l>>3, unit u = 8w + (l&7)).
// Gate exchange via 3 warp shfls (no smem, no barrier); h double-buffered in
// smem -> exactly ONE __syncthreads per step.
// ---------------------------------------------------------------------------
__global__ __launch_bounds__(256,2) void lstm_kernel(
    const float* __restrict__ wd_x, const float* __restrict__ rd_x,
    const float* __restrict__ wd_Wih, const float* __restrict__ wd_Whh,
    const float* __restrict__ wd_bih, const float* __restrict__ wd_bhh,
    const float* __restrict__ rd_Wih, const float* __restrict__ rd_Whh,
    const float* __restrict__ rd_bih, const float* __restrict__ rd_bhh)
{
    int idx = blockIdx.x;
    int br = idx >> 10;
    int b  = (idx >> 4) & 63;
    int f  = idx & 15;
    const float* x   = br ? rd_x   : wd_x;
    const float* Wih = br ? rd_Wih : wd_Wih;
    const float* Whh = br ? rd_Whh : wd_Whh;
    const float* bih = br ? rd_bih : wd_bih;
    const float* bhh = br ? rd_bhh : wd_bhh;

    int g = threadIdx.x;
    int w = g >> 5, l = g & 31;
    int gt = l >> 3, ul = l & 7;
    int u  = w*8 + ul;              // unit 0..63
    int row = gt*64 + u;            // gate row in [i|f|g|o] layout

    __shared__ __align__(16) float sh_h[2][64];
    __shared__ float sh_x[128];

    float wrow[64];
    {
        const float4* wr4 = (const float4*)(Whh + ((size_t)f*256 + row)*64);
        #pragma unroll
        for (int j = 0; j < 16; j++) {
            float4 v = wr4[j];
            wrow[4*j+0]=v.x; wrow[4*j+1]=v.y; wrow[4*j+2]=v.z; wrow[4*j+3]=v.w;
        }
    }
    float wih  = Wih[f*256+row];
    float bias = bih[f*256+row] + bhh[f*256+row];
    if (g < 128) sh_x[g] = x[((size_t)b*128 + g)*16 + f];
    if (g < 64)  sh_h[0][g] = 0.f;
    float c = 0.f;
    float* outp = g_lstm + (((size_t)br*BB + b)*FF + f)*(size_t)(SS*HH) + u;
    __syncthreads();

    #pragma unroll 1
    for (int s = 0; s < 128; s++) {
        const float* hin = sh_h[s & 1];
        float a0=0.f,a1=0.f,a2=0.f,a3=0.f;
        #pragma unroll
        for (int j = 0; j < 64; j += 4) {
            a0 = fmaf(wrow[j+0], hin[j+0], a0);
            a1 = fmaf(wrow[j+1], hin[j+1], a1);
            a2 = fmaf(wrow[j+2], hin[j+2], a2);
            a3 = fmaf(wrow[j+3], hin[j+3], a3);
        }
        float gate = fmaf(sh_x[s], wih, bias) + ((a0+a1)+(a2+a3));
        // gather the 4 gates of unit u onto the gt==0 lane
        float vf = __shfl_down_sync(0xffffffffu, gate, 8);
        float vg = __shfl_down_sync(0xffffffffu, gate, 16);
        float vo = __shfl_down_sync(0xffffffffu, gate, 24);
        if (gt == 0) {
            float ig = sigf(gate);
            float fg = sigf(vf);
            float gg = tanh_approx(vg);
            float og = sigf(vo);
            c = fg*c + ig*gg;
            float h = og*tanh_approx(c);
            sh_h[(s+1)&1][u] = h;
            outp[s*64] = h;
        }
        __syncthreads();
    }
}

// ---------------------------------------------------------------------------
// Attention: one block per (branch, b, f). 128 threads; thread t = query row t.
// Two-pass softmax (no max-subtraction; scores are tiny), no score buffers.
// Pass1/Pass2 k-loops 2-way interleaved (xp dead there; no spill).
// ---------------------------------------------------------------------------
#define KV_STRIDE 68
#define SM_K     0
#define SM_V     (128*KV_STRIDE)
#define SM_WBUF  (2*128*KV_STRIDE)            // 2048 floats
#define SM_WTR   (SM_WBUF + 2048)             // 128*33 = 4224 floats
#define SM_BIN   (SM_WTR + 128*33)            // 192
#define SM_BOUT  (SM_BIN + 192)               // 64
#define SM_RED   (SM_BOUT + 64)               // 256
#define ATTN_SMEM_FLOATS (SM_RED + 256)
#define ATTN_SMEM_BYTES  (ATTN_SMEM_FLOATS*4)

__global__ __launch_bounds__(128,2) void attn_kernel(
    const float* __restrict__ wd_aw, const float* __restrict__ wd_ab,
    const float* __restrict__ wd_ow, const float* __restrict__ wd_ob,
    const float* __restrict__ rd_aw, const float* __restrict__ rd_ab,
    const float* __restrict__ rd_ow, const float* __restrict__ rd_ob,
    float* __restrict__ out_base)
{
    extern __shared__ __align__(16) float sm[];
    float* Ksm   = sm + SM_K;
    float* Vsm   = sm + SM_V;
    float* Wbuf  = sm + SM_WBUF;
    float* wtr   = sm + SM_WTR;
    float* binsm = sm + SM_BIN;
    float* boutsm= sm + SM_BOUT;
    float* red   = sm + SM_RED;

    int idx = blockIdx.x;
    int br = idx >> 10;
    int b  = (idx >> 4) & 63;
    int f  = idx & 15;
    int t  = threadIdx.x;
    const float* aw = (br ? rd_aw : wd_aw) + (size_t)f*192*64;
    const float* ab = (br ? rd_ab : wd_ab) + f*192;
    const float* ow = (br ? rd_ow : wd_ow) + (size_t)f*64*64;
    const float* ob = (br ? rd_ob : wd_ob) + f*64;

    for (int i = t; i < 192; i += 128) binsm[i] = ab[i];
    if (t < 64) boutsm[t] = ob[t];

    // my LSTM row (S-position t), packed
    u64 xp[32];
    {
        const ulonglong2* X2 = (const ulonglong2*)(g_lstm +
            (((size_t)br*BB + b)*FF + f)*(size_t)(SS*HH) + (size_t)t*64);
        #pragma unroll
        for (int j = 0; j < 16; j++) {
            ulonglong2 v = X2[j];
            xp[2*j] = v.x; xp[2*j+1] = v.y;
        }
    }

    // ---- Phase A: QKV projection in 32-row weight chunks ----
    #pragma unroll 1
    for (int c = 0; c < 2; c++) {            // K
        __syncthreads();
        const float4* src = (const float4*)(aw + (size_t)(64 + 32*c)*64);
        for (int i = t; i < 512; i += 128) ((float4*)Wbuf)[i] = src[i];
        __syncthreads();
        #pragma unroll 1
        for (int r = 0; r < 32; r++) {
            float v = dot64p(Wbuf + r*64, xp) + binsm[64 + 32*c + r];
            Ksm[t*KV_STRIDE + 32*c + r] = v;
        }
    }
    #pragma unroll 1
    for (int c = 0; c < 2; c++) {            // V
        __syncthreads();
        const float4* src = (const float4*)(aw + (size_t)(128 + 32*c)*64);
        for (int i = t; i < 512; i += 128) ((float4*)Wbuf)[i] = src[i];
        __syncthreads();
        #pragma unroll 1
        for (int r = 0; r < 32; r++) {
            float v = dot64p(Wbuf + r*64, xp) + binsm[128 + 32*c + r];
            Vsm[t*KV_STRIDE + 32*c + r] = v;
        }
    }
    u64 qp[32];
    #pragma unroll 1
    for (int c = 0; c < 2; c++) {            // q (kept packed in regs)
        __syncthreads();
        const float4* src = (const float4*)(aw + (size_t)(32*c)*64);
        for (int i = t; i < 512; i += 128) ((float4*)Wbuf)[i] = src[i];
        __syncthreads();
        if (c == 0) {
            #pragma unroll
            for (int i = 0; i < 16; i++) {
                float d0 = dot64p(Wbuf + (2*i)*64,   xp) + binsm[2*i];
                float d1 = dot64p(Wbuf + (2*i+1)*64, xp) + binsm[2*i+1];
                qp[i] = pk2(d0, d1);
            }
        } else {
            #pragma unroll
            for (int i = 0; i < 16; i++) {
                float d0 = dot64p(Wbuf + (2*i)*64,   xp) + binsm[32+2*i];
                float d1 = dot64p(Wbuf + (2*i+1)*64, xp) + binsm[32+2*i+1];
                qp[16+i] = pk2(d0, d1);
            }
        }
    }
    // fold score scale 1/sqrt(32) into q
    {
        const float scale = 0.1767766952966369f;
        u64 sc = pk2(scale, scale);
        #pragma unroll
        for (int j = 0; j < 32; j++) qp[j] = fmul2(qp[j], sc);
    }

    // ---- Pass 1: scores -> exp (no max-sub) -> unnormalized O + sums ----
    // 2-way k interleave for latency hiding (xp dead; ~180 live regs, no spill)
    u64 op[32];
    #pragma unroll
    for (int j = 0; j < 32; j++) op[j] = 0ull;
    float sum0 = 0.f, sum1 = 0.f;
    #pragma unroll 1
    for (int k = 0; k < 128; k += 2) {
        const ulonglong2* KrA = (const ulonglong2*)(Ksm + k*KV_STRIDE);
        const ulonglong2* KrB = (const ulonglong2*)(Ksm + (k+1)*KV_STRIDE);
        u64 a0=0ull,a1=0ull,a2=0ull,a3=0ull;
        u64 b0=0ull,b1=0ull,b2=0ull,b3=0ull;
        #pragma unroll
        for (int j = 0; j < 8; j++) {
            ulonglong2 ka = KrA[j];
            ulonglong2 kb = KrB[j];
            a0 = ffma2(ka.x, qp[2*j],   a0);
            a1 = ffma2(ka.y, qp[2*j+1], a1);
            b0 = ffma2(kb.x, qp[2*j],   b0);
            b1 = ffma2(kb.y, qp[2*j+1], b1);
        }
        #pragma unroll
        for (int j = 8; j < 16; j++) {
            ulonglong2 ka = KrA[j];
            ulonglong2 kb = KrB[j];
            a2 = ffma2(ka.x, qp[2*j],   a2);
            a3 = ffma2(ka.y, qp[2*j+1], a3);
            b2 = ffma2(kb.x, qp[2*j],   b2);
            b3 = ffma2(kb.y, qp[2*j+1], b3);
        }
        float s0a = hsum2(fadd2(a0,a1)), s1a = hsum2(fadd2(a2,a3));
        float s0b = hsum2(fadd2(b0,b1)), s1b = hsum2(fadd2(b2,b3));
        float e0a = __expf(s0a), e1a = __expf(s1a);
        float e0b = __expf(s0b), e1b = __expf(s1b);
        sum0 += e0a + e0b; sum1 += e1a + e1b;
        u64 w0a = pk2(e0a,e0a), w1a = pk2(e1a,e1a);
        u64 w0b = pk2(e0b,e0b), w1b = pk2(e1b,e1b);
        const ulonglong2* VrA = (const ulonglong2*)(Vsm + k*KV_STRIDE);
        const ulonglong2* VrB = (const ulonglong2*)(Vsm + (k+1)*KV_STRIDE);
        #pragma unroll
        for (int j = 0; j < 8; j++) {
            ulonglong2 va = VrA[j];
            ulonglong2 vb = VrB[j];
            op[2*j]   = ffma2(w0a, va.x, op[2*j]);
            op[2*j+1] = ffma2(w0a, va.y, op[2*j+1]);
            op[2*j]   = ffma2(w0b, vb.x, op[2*j]);
            op[2*j+1] = ffma2(w0b, vb.y, op[2*j+1]);
        }
        #pragma unroll
        for (int j = 8; j < 16; j++) {
            ulonglong2 va = VrA[j];
            ulonglong2 vb = VrB[j];
            op[2*j]   = ffma2(w1a, va.x, op[2*j]);
            op[2*j+1] = ffma2(w1a, va.y, op[2*j+1]);
            op[2*j]   = ffma2(w1b, vb.x, op[2*j]);
            op[2*j+1] = ffma2(w1b, vb.y, op[2*j+1]);
        }
    }
    float inv0 = 1.f/sum0, inv1 = 1.f/sum1;
    {
        u64 i0 = pk2(inv0, inv0), i1 = pk2(inv1, inv1);
        #pragma unroll
        for (int j = 0; j < 16; j++) op[j] = fmul2(op[j], i0);
        #pragma unroll
        for (int j = 16; j < 32; j++) op[j] = fmul2(op[j], i1);
    }

    // ---- Pass 2: recompute scores, write head-avg attn weights ----
    float* outw = out_base + 128 + (size_t)br*ATTN_ELEMS + (((size_t)f*64 + b) << 14);
    #pragma unroll 1
    for (int kc = 0; kc < 4; kc++) {
        #pragma unroll 1
        for (int kk = 0; kk < 32; kk += 2) {
            int k = kc*32 + kk;
            const ulonglong2* KrA = (const ulonglong2*)(Ksm + k*KV_STRIDE);
            const ulonglong2* KrB = (const ulonglong2*)(Ksm + (k+1)*KV_STRIDE);
            u64 a0=0ull,a1=0ull,a2=0ull,a3=0ull;
            u64 b0=0ull,b1=0ull,b2=0ull,b3=0ull;
            #pragma unroll
            for (int j = 0; j < 8; j++) {
                ulonglong2 ka = KrA[j];
                ulonglong2 kb = KrB[j];
                a0 = ffma2(ka.x, qp[2*j],   a0);
                a1 = ffma2(ka.y, qp[2*j+1], a1);
                b0 = ffma2(kb.x, qp[2*j],   b0);
                b1 = ffma2(kb.y, qp[2*j+1], b1);
            }
            #pragma unroll
            for (int j = 8; j < 16; j++) {
                ulonglong2 ka = KrA[j];
                ulonglong2 kb = KrB[j];
                a2 = ffma2(ka.x, qp[2*j],   a2);
                a3 = ffma2(ka.y, qp[2*j+1], a3);
                b2 = ffma2(kb.x, qp[2*j],   b2);
                b3 = ffma2(kb.y, qp[2*j+1], b3);
            }
            float s0a = hsum2(fadd2(a0,a1)), s1a = hsum2(fadd2(a2,a3));
            float s0b = hsum2(fadd2(b0,b1)), s1b = hsum2(fadd2(b2,b3));
            wtr[t*33 + kk]   = 0.5f*(__expf(s0a)*inv0 + __expf(s1a)*inv1);
            wtr[t*33 + kk+1] = 0.5f*(__expf(s0b)*inv0 + __expf(s1b)*inv1);
        }
        __syncthreads();
        for (int i = t; i < 4096; i += 128) {
            int r = i >> 5, cc = i & 31;
            outw[r*128 + kc*32 + cc] = wtr[r*33 + cc];
        }
        __syncthreads();
    }

    // ---- Phase C: out-projection + mean over S. Stage Wout into Ksm. ----
    for (int i = t; i < 1024; i += 128) ((float4*)Ksm)[i] = ((const float4*)ow)[i];
    __syncthreads();
    int lane = t & 31, warp = t >> 5;
    #pragma unroll 1
    for (int o = 0; o < 64; o++) {
        float acc = dot64p(Ksm + o*64, op);
        #pragma unroll
        for (int off = 16; off; off >>= 1)
            acc += __shfl_down_sync(0xffffffffu, acc, off);
        if (lane == 0) red[warp*64 + o] = acc;
    }
    __syncthreads();
    if (t < 64) {
        float s = red[t] + red[64+t] + red[128+t] + red[192+t];
        g_pooled[(((size_t)br*BB + b)*FF + f)*HH + t] = s*(1.f/128.f) + boutsm[t];
    }
}

// ---------------------------------------------------------------------------
// Head: static/time MLPs + final fc. One block, thread = batch row.
// ---------------------------------------------------------------------------
__global__ __launch_bounds__(64) void head_kernel(
    const float* __restrict__ stat, const float* __restrict__ tg,
    const float* __restrict__ d1w, const float* __restrict__ d1b,
    const float* __restrict__ d2w, const float* __restrict__ d2b,
    const float* __restrict__ t1w, const float* __restrict__ t1b,
    const float* __restrict__ t2w, const float* __restrict__ t2b,
    const float* __restrict__ fcw, const float* __restrict__ fcb,
    float* __restrict__ out)
{
    int b = threadIdx.x;
    float s1[64];
    #pragma unroll
    for (int j = 0; j < 64; j++) {
        float acc = d1b[j];
        #pragma unroll
        for (int k = 0; k < 32; k++) acc += stat[b*32+k]*d1w[j*32+k];
        s1[j] = fmaxf(acc, 0.f);
    }
    float s2[32];
    #pragma unroll
    for (int j = 0; j < 32; j++) {
        float acc = d2b[j];
        #pragma unroll
        for (int k = 0; k < 64; k++) acc += s1[k]*d2w[j*64+k];
        s2[j] = fmaxf(acc, 0.f);
    }
    float tv = tg[b];
    float tt1[16];
    #pragma unroll
    for (int j = 0; j < 16; j++) tt1[j] = fmaxf(t1b[j] + tv*t1w[j], 0.f);
    float tt2[8];
    #pragma unroll
    for (int j = 0; j < 8; j++) {
        float acc = t2b[j];
        #pragma unroll
        for (int k = 0; k < 16; k++) acc += tt1[k]*t2w[j*16+k];
        tt2[j] = fmaxf(acc, 0.f);
    }
    const float* p_wd = g_pooled + (size_t)b*1024;
    const float* p_rd = g_pooled + 65536u + (size_t)b*1024;
    #pragma unroll
    for (int o = 0; o < 2; o++) {
        const float* w = fcw + o*2088;
        float acc = fcb[o];
        for (int i = 0; i < 1024; i++) acc += p_wd[i]*w[i];
        for (int i = 0; i < 1024; i++) acc += p_rd[i]*w[1024+i];
        #pragma unroll
        for (int k = 0; k < 32; k++) acc += s2[k]*w[2048+k];
        #pragma unroll
        for (int k = 0; k < 8; k++)  acc += tt2[k]*w[2080+k];
        out[b*2+o] = acc;
    }
}

// ---------------------------------------------------------------------------
extern "C" void kernel_launch(void* const* d_in, const int* in_sizes, int n_in,
                              void* d_out, int out_size)
{
    const float* wd_x   = (const float*)d_in[0];
    const float* rd_x   = (const float*)d_in[1];
    const float* stat   = (const float*)d_in[2];
    const float* tg     = (const float*)d_in[3];
    const float* wd_Wih = (const float*)d_in[4];
    const float* wd_Whh = (const float*)d_in[5];
    const float* wd_bih = (const float*)d_in[6];
    const float* wd_bhh = (const float*)d_in[7];
    const float* rd_Wih = (const float*)d_in[8];
    const float* rd_Whh = (const float*)d_in[9];
    const float* rd_bih = (const float*)d_in[10];
    const float* rd_bhh = (const float*)d_in[11];
    const float* wd_aw  = (const float*)d_in[12];
    const float* wd_ab  = (const float*)d_in[13];
    const float* wd_ow  = (const float*)d_in[14];
    const float* wd_ob  = (const float*)d_in[15];
    const float* rd_aw  = (const float*)d_in[16];
    const float* rd_ab  = (const float*)d_in[17];
    const float* rd_ow  = (const float*)d_in[18];
    const float* rd_ob  = (const float*)d_in[19];
    const float* d1w = (const float*)d_in[20];
    const float* d1b = (const float*)d_in[21];
    const float* d2w = (const float*)d_in[22];
    const float* d2b = (const float*)d_in[23];
    const float* t1w = (const float*)d_in[24];
    const float* t1b = (const float*)d_in[25];
    const float* t2w = (const float*)d_in[26];
    const float* t2b = (const float*)d_in[27];
    const float* fcw = (const float*)d_in[28];
    const float* fcb = (const float*)d_in[29];
    float* out = (float*)d_out;

    cudaFuncSetAttribute(attn_kernel,
                         cudaFuncAttributeMaxDynamicSharedMemorySize,
                         ATTN_SMEM_BYTES);

    lstm_kernel<<<2048, 256>>>(wd_x, rd_x, wd_Wih, wd_Whh, wd_bih, wd_bhh,
                               rd_Wih, rd_Whh, rd_bih, rd_bhh);
    attn_kernel<<<2048, 128, ATTN_SMEM_BYTES>>>(wd_aw, wd_ab, wd_ow, wd_ob,
                                                rd_aw, rd_ab, rd_ow, rd_ob, out);
    head_kernel<<<1, 64>>>(stat, tg, d1w, d1b, d2w, d2b,
                           t1w, t1b, t2w, t2b, fcw, fcb, out);
}